// round 7
// baseline (speedup 1.0000x reference)
#include <cuda_runtime.h>

#define TT 512
#define BB 256
#define II 64
#define HH 512
#define G3 1536
#define RT (TT*BB)
#define KC 64
#define NCH (HH/KC)      // 8
#define AS 68            // row stride (floats) for KC=64 chunks
#define ASZ (32*AS)      // 2176 floats per A buffer
#define BSZ (96*AS)      // 6528 floats per B buffer
#define SMEM_BYTES (4*(ASZ+BSZ)*4)   // 139264

typedef unsigned long long u64;

__device__ float g_giT[(size_t)TT * G3 * BB];   // [t][gate*H+unit][batch]
__device__ float g_Z  [(size_t)RT * HH];        // [t][b][h]
__device__ float g_h0 [BB * HH];                // zeros
struct __align__(128) Bar { unsigned cnt; unsigned gen; unsigned pad[30]; };
__device__ Bar g_bar[8];

__device__ __forceinline__ u64 ffma2(u64 a, u64 b, u64 c){
    u64 d;
    asm("fma.rn.f32x2 %0, %1, %2, %3;" : "=l"(d) : "l"(a), "l"(b), "l"(c));
    return d;
}
__device__ __forceinline__ float pairsum(u64 v){
    float lo, hi;
    asm("mov.b64 {%0, %1}, %2;" : "=f"(lo), "=f"(hi) : "l"(v));
    return lo + hi;
}
__device__ __forceinline__ float sigf(float x){
    return __fdividef(1.0f, 1.0f + __expf(-x));
}
__device__ __forceinline__ void cpa16(float* dst, const float* src){
    unsigned d = (unsigned)__cvta_generic_to_shared(dst);
    asm volatile("cp.async.ca.shared.global [%0], [%1], 16;" :: "r"(d), "l"(src));
}
__device__ __forceinline__ void cpa_commit(){ asm volatile("cp.async.commit_group;"); }

// ---------------- Phase 1: giT[t][c][b] = X[t,b,:] . Wih[c,:] + bih[c] ----------------
#define GIS 66
__global__ __launch_bounds__(256) void gi_kernel(const float* __restrict__ X,
                                                 const float* __restrict__ Wih,
                                                 const float* __restrict__ bih)
{
    __shared__ __align__(16) float Xs[64 * GIS];
    __shared__ __align__(16) float Ws[64 * GIS];
    const int r0 = blockIdx.x * 64;
    const int c0 = blockIdx.y * 64;
    const int t  = threadIdx.x;

    #pragma unroll
    for (int j = 0; j < 4; j++){
        int q   = t + 256 * j;
        int row = q >> 4;
        int kq  = q & 15;
        const u64* gx = reinterpret_cast<const u64*>(&X[(size_t)(r0+row)*II + kq*4]);
        u64* px = reinterpret_cast<u64*>(&Xs[row*GIS + kq*4]);
        px[0] = gx[0]; px[1] = gx[1];
        const u64* gw = reinterpret_cast<const u64*>(&Wih[(size_t)(c0+row)*II + kq*4]);
        u64* pw = reinterpret_cast<u64*>(&Ws[row*GIS + kq*4]);
        pw[0] = gw[0]; pw[1] = gw[1];
    }
    __syncthreads();

    const int tm = t & 15;
    const int tn = t >> 4;
    u64 acc[4][4];
    #pragma unroll
    for (int i = 0; i < 4; i++)
        #pragma unroll
        for (int j = 0; j < 4; j++) acc[i][j] = 0ull;

    #pragma unroll 8
    for (int k = 0; k < 64; k += 2){
        u64 a[4], b[4];
        #pragma unroll
        for (int i = 0; i < 4; i++)
            a[i] = *reinterpret_cast<const u64*>(&Xs[(tm+16*i)*GIS + k]);
        #pragma unroll
        for (int j = 0; j < 4; j++)
            b[j] = *reinterpret_cast<const u64*>(&Ws[(tn+16*j)*GIS + k]);
        #pragma unroll
        for (int i = 0; i < 4; i++)
            #pragma unroll
            for (int j = 0; j < 4; j++)
                acc[i][j] = ffma2(a[i], b[j], acc[i][j]);
    }

    #pragma unroll
    for (int i = 0; i < 4; i++){
        #pragma unroll
        for (int j = 0; j < 4; j++){
            int c = c0 + tn + 16*j;
            int r = r0 + tm + 16*i;
            g_giT[((size_t)(r >> 8) * G3 + c) * BB + (r & 255)] = pairsum(acc[i][j]) + bih[c];
        }
    }
}

// ---------------- Phase 2: persistent GRU, 256 thr/CTA, 4-buf pipeline ----------------
__global__ __launch_bounds__(256, 1) void step_persist(const float* __restrict__ Whh,
                                                       const float* __restrict__ bhh)
{
    extern __shared__ __align__(16) float sm[];
    float* Asb = sm;               // [4][ASZ]
    float* Bsb = sm + 4*ASZ;       // [4][BSZ]

    const int bx  = blockIdx.x;          // 8 batch groups
    const int b0  = bx * 32;
    const int h0  = blockIdx.y * 32;     // 16 hidden groups
    const int tid = threadIdx.x;
    const int mq  = tid & 7;             // batches b0 + mq + 8i
    const int u   = tid >> 3;            // unit h0 + u (0..31)
    const int jg  = h0 + u;

    const float bhr = bhh[jg], bhz = bhh[HH + jg], bhn = bhh[2*HH + jg];

    // load maps (per chunk): A 2 float4/thread, B 6 float4/thread
    const int aRow = tid >> 4;           // used with jj offset
    int bRowS[6], bRowG[6], bKq[6];
    #pragma unroll
    for (int jj = 0; jj < 6; jj++){
        int idx = tid + 256*jj;          // 0..1535
        int row = idx >> 4;              // 0..95
        bKq[jj]  = idx & 15;
        bRowS[jj]= row;
        bRowG[jj]= (row >> 5) * HH + h0 + (row & 31);
    }

    unsigned gen;
    asm volatile("ld.acquire.gpu.u32 %0, [%1];" : "=r"(gen) : "l"(&g_bar[bx].gen) : "memory");

    for (int t = 0; t < TT; t++){
        const float* hprev = (t == 0) ? g_h0 : (g_Z + (size_t)(t-1)*BB*HH);
        float*       hout  = g_Z + (size_t)t * BB * HH;
        const float* git   = g_giT + (size_t)t * G3 * BB;

        // epilogue operand prefetch (registers)
        float gv[3][4], hp[4];
        #pragma unroll
        for (int i = 0; i < 4; i++){
            int b = b0 + mq + 8*i;
            gv[0][i] = git[(size_t)(        jg)*BB + b];
            gv[1][i] = git[(size_t)(HH   + jg)*BB + b];
            gv[2][i] = git[(size_t)(2*HH + jg)*BB + b];
            hp[i]    = hprev[(size_t)b*HH + jg];
        }

        // prologue: chunks 0,1
        #pragma unroll
        for (int p = 0; p < 2; p++){
            int k0 = p * KC;
            #pragma unroll
            for (int jj = 0; jj < 2; jj++){
                int idx = tid + 256*jj, row = idx >> 4, kq = idx & 15;
                cpa16(&Asb[p*ASZ + row*AS + kq*4], &hprev[(size_t)(b0+row)*HH + k0 + kq*4]);
            }
            #pragma unroll
            for (int jj = 0; jj < 6; jj++)
                cpa16(&Bsb[p*BSZ + bRowS[jj]*AS + bKq[jj]*4], &Whh[(size_t)bRowG[jj]*HH + k0 + bKq[jj]*4]);
            cpa_commit();
        }

        u64 accr[4], accz[4], accn[4];
        #pragma unroll
        for (int i = 0; i < 4; i++){ accr[i]=0ull; accz[i]=0ull; accn[i]=0ull; }

        #pragma unroll 1
        for (int c = 0; c < NCH; c++){
            if (c + 2 < NCH){
                int nb = (c+2) & 3, k0 = (c+2)*KC;
                #pragma unroll
                for (int jj = 0; jj < 2; jj++){
                    int idx = tid + 256*jj, row = idx >> 4, kq = idx & 15;
                    cpa16(&Asb[nb*ASZ + row*AS + kq*4], &hprev[(size_t)(b0+row)*HH + k0 + kq*4]);
                }
                #pragma unroll
                for (int jj = 0; jj < 6; jj++)
                    cpa16(&Bsb[nb*BSZ + bRowS[jj]*AS + bKq[jj]*4], &Whh[(size_t)bRowG[jj]*HH + k0 + bKq[jj]*4]);
                cpa_commit();
            }
            if (c < NCH-2)      asm volatile("cp.async.wait_group 2;");
            else if (c == NCH-2) asm volatile("cp.async.wait_group 1;");
            else                 asm volatile("cp.async.wait_group 0;");
            __syncthreads();

            const int buf = c & 3;
            const float* Ab = Asb + buf*ASZ;
            const float* Bb = Bsb + buf*BSZ;
            #pragma unroll 8
            for (int k = 0; k < KC; k += 2){
                u64 br = *reinterpret_cast<const u64*>(&Bb[(     u)*AS + k]);
                u64 bz = *reinterpret_cast<const u64*>(&Bb[(32 + u)*AS + k]);
                u64 bn = *reinterpret_cast<const u64*>(&Bb[(64 + u)*AS + k]);
                #pragma unroll
                for (int i = 0; i < 4; i++){
                    u64 a = *reinterpret_cast<const u64*>(&Ab[(mq+8*i)*AS + k]);
                    accr[i] = ffma2(a, br, accr[i]);
                    accz[i] = ffma2(a, bz, accz[i]);
                    accn[i] = ffma2(a, bn, accn[i]);
                }
            }
        }

        // fused gate epilogue
        #pragma unroll
        for (int i = 0; i < 4; i++){
            int b = b0 + mq + 8*i;
            float pr = pairsum(accr[i]) + bhr;
            float pz = pairsum(accz[i]) + bhz;
            float pn = pairsum(accn[i]) + bhn;
            float r  = sigf(gv[0][i] + pr);
            float z  = sigf(gv[1][i] + pz);
            float nn = tanhf(gv[2][i] + r * pn);
            hout[(size_t)b*HH + jg] = (1.0f - z) * nn + z * hp[i];
        }

        // bx-group barrier (16 CTAs)
        __syncthreads();
        if (tid == 0){
            __threadfence();
            unsigned arr = atomicAdd(&g_bar[bx].cnt, 1);
            if (arr == 15){
                atomicExch(&g_bar[bx].cnt, 0);
                __threadfence();
                atomicAdd(&g_bar[bx].gen, 1);
            } else {
                unsigned g;
                do {
                    __nanosleep(32);
                    asm volatile("ld.acquire.gpu.u32 %0, [%1];" : "=r"(g) : "l"(&g_bar[bx].gen) : "memory");
                } while (g == gen);
            }
            gen++;
        }
        __syncthreads();
    }
}

// ---------------- Phase 3: V = bias + Z . vw ----------------
__global__ __launch_bounds__(256) void value_kernel(const float* __restrict__ vw,
                                                    const float* __restrict__ bias,
                                                    float* __restrict__ out)
{
    int warp = (blockIdx.x * 256 + threadIdx.x) >> 5;
    int lane = threadIdx.x & 31;
    const float* z = g_Z + (size_t)warp * HH;
    float s = 0.0f;
    #pragma unroll
    for (int i = 0; i < 4; i++){
        int idx = i*128 + lane*4;
        float4 zv = *reinterpret_cast<const float4*>(&z[idx]);
        float4 wv = *reinterpret_cast<const float4*>(&vw[idx]);
        s += zv.x*wv.x + zv.y*wv.y + zv.z*wv.z + zv.w*wv.w;
    }
    #pragma unroll
    for (int o = 16; o > 0; o >>= 1)
        s += __shfl_xor_sync(0xFFFFFFFFu, s, o);
    if (lane == 0) out[warp] = s + bias[0];
}

extern "C" void kernel_launch(void* const* d_in, const int* in_sizes, int n_in,
                              void* d_out, int out_size)
{
    const float* X    = (const float*)d_in[0];
    const float* Wih  = (const float*)d_in[1];
    const float* Whh  = (const float*)d_in[2];
    const float* bih  = (const float*)d_in[3];
    const float* bhh  = (const float*)d_in[4];
    const float* vw   = (const float*)d_in[5];
    const float* bias = (const float*)d_in[6];
    float* out = (float*)d_out;

    static int smem_set = 0;
    if (!smem_set){
        cudaFuncSetAttribute(step_persist, cudaFuncAttributeMaxDynamicSharedMemorySize, SMEM_BYTES);
        smem_set = 1;
    }

    dim3 ggi(RT/64, G3/64);
    gi_kernel<<<ggi, 256>>>(X, Wih, bih);

    dim3 gst(BB/32, HH/32);   // 8 x 16 = 128 CTAs, all resident
    step_persist<<<gst, 256, SMEM_BYTES>>>(Whh, bhh);

    value_kernel<<<RT/8, 256>>>(vw, bias, out);
}